// round 2
// baseline (speedup 1.0000x reference)
#include <cuda_runtime.h>

// Problem constants (fixed by reference_code)
#define H    20     // hidden size
#define G4   80     // 4*H gates
#define FIN  10     // input features
#define NW   4      // warps (=batches) per CTA
#define THREADS (NW*32)

typedef unsigned long long u64;

// ---- packed f32x2 helpers (Blackwell sm_100+; FFMA2 only reachable via PTX) ----
__device__ __forceinline__ u64 pk2(float lo, float hi) {
    u64 r; asm("mov.b64 %0, {%1,%2};" : "=l"(r) : "f"(lo), "f"(hi)); return r;
}
__device__ __forceinline__ void fma2(u64 &d, u64 a, u64 b) {
    asm("fma.rn.f32x2 %0, %1, %2, %0;" : "+l"(d) : "l"(a), "l"(b));
}
__device__ __forceinline__ float hadd2(u64 v) {
    float lo, hi; asm("mov.b64 {%0,%1}, %2;" : "=f"(lo), "=f"(hi) : "l"(v)); return lo + hi;
}

// act = A * sigmoid(-fm*pre) + Bc  with sigmoid(z)=1/(1+e^-z)
//   sigmoid: fm=-1, A=1, Bc=0 ;  tanh: fm=-2, A=2, Bc=-1  (tanh(x)=2*sig(2x)-1)
__device__ __forceinline__ float act_eval(float pre, float fm, float A, float Bc) {
    float e = __expf(fm * pre);
    float y = __fdividef(1.0f, 1.0f + e);
    return fmaf(A, y, Bc);
}

__global__ void __launch_bounds__(THREADS, 1)
lstm2_fused_kernel(const float* __restrict__ x,
                   const float* __restrict__ w_ih0, const float* __restrict__ w_hh0,
                   const float* __restrict__ b_ih0, const float* __restrict__ b_hh0,
                   const float* __restrict__ w_ih1, const float* __restrict__ w_hh1,
                   const float* __restrict__ b_ih1, const float* __restrict__ b_hh1,
                   const float* __restrict__ w_fc,  const float* __restrict__ b_fc,
                   float* __restrict__ out, int T, int B)
{
    // --- shared memory ---
    __shared__ __align__(16) u64   s_wih0[G4 * 5];   // x-projection weights, packed pairs [g][k2]
    __shared__ float s_b0[G4], s_b1[G4];             // bias sums (b_ih + b_hh)
    __shared__ __align__(16) float s_h1[NW][24];     // layer-1 hidden (pad to 24)
    __shared__ __align__(16) float s_h2[NW][24];     // layer-2 hidden
    __shared__ float s_g[NW][G4];                    // activated gates scratch
    __shared__ __align__(16) float s_x[NW][12];      // staged x_t (pad to 12)

    const int tid  = threadIdx.x;
    const int w    = tid >> 5;
    const int lane = tid & 31;
    const int b    = blockIdx.x * NW + w;

    // cooperative weight staging
    for (int i = tid; i < G4 * 5; i += THREADS) {
        int g = i / 5, k2 = i % 5;
        s_wih0[i] = pk2(w_ih0[g * FIN + 2 * k2], w_ih0[g * FIN + 2 * k2 + 1]);
    }
    for (int i = tid; i < G4; i += THREADS) {
        s_b0[i] = b_ih0[i] + b_hh0[i];
        s_b1[i] = b_ih1[i] + b_hh1[i];
    }
    if (lane < 24) { s_h1[w][lane] = 0.0f; s_h2[w][lane] = 0.0f; }
    __syncthreads();

    if (b >= B) return;

    // gate slots for this lane
    const int g0 = lane;
    const int g1 = lane + 32;
    const int g2 = (lane < 16) ? (lane + 64) : (lane + 32); // clamped; slot2 result masked
    int gs[3] = {g0, g1, g2};

    // per-slot activation constants (g in [40,60) -> tanh, else sigmoid)
    float fmc[3], Ac[3], Bcc[3];
#pragma unroll
    for (int s = 0; s < 3; s++) {
        bool th = (gs[s] >= 40) && (gs[s] < 60);
        fmc[s] = th ? -2.0f : -1.0f;
        Ac[s]  = th ?  2.0f :  1.0f;
        Bcc[s] = th ? -1.0f :  0.0f;
    }

    // recurrent weights -> registers, packed f32x2 (rows are 20 floats = 8B aligned)
    u64 wh0[3][10], wx1[3][10], wh1[3][10];
    {
        const u64* p0 = reinterpret_cast<const u64*>(w_hh0);
        const u64* p1 = reinterpret_cast<const u64*>(w_ih1);
        const u64* p2 = reinterpret_cast<const u64*>(w_hh1);
#pragma unroll
        for (int s = 0; s < 3; s++) {
            int base = gs[s] * 10;
#pragma unroll
            for (int k = 0; k < 10; k++) {
                wh0[s][k] = p0[base + k];
                wx1[s][k] = p1[base + k];
                wh1[s][k] = p2[base + k];
            }
        }
    }

    const float* xrow = x + (size_t)b * T * FIN;
    const u64* h1p = reinterpret_cast<const u64*>(s_h1[w]);
    const u64* h2p = reinterpret_cast<const u64*>(s_h2[w]);
    const u64* xpp = reinterpret_cast<const u64*>(s_x[w]);

    float c1 = 0.0f, c2 = 0.0f, h2v = 0.0f;
    float wfc = (lane < H) ? w_fc[lane] : 0.0f;

    float xv = 0.0f;
    if (lane < FIN) xv = xrow[lane];   // prefetch t=0

#pragma unroll 1
    for (int t = 0; t < T; t++) {
        // stage x_t, prefetch x_{t+1}
        if (lane < FIN) s_x[w][lane] = xv;
        __syncwarp();
        if (lane < FIN) xv = (t + 1 < T) ? xrow[(t + 1) * FIN + lane] : 0.0f;

        // ================= layer 1 gates =================
        u64 a0 = pk2(s_b0[g0], 0.0f);
        u64 a1 = pk2(s_b0[g1], 0.0f);
        u64 a2 = pk2(s_b0[g2], 0.0f);
#pragma unroll
        for (int k = 0; k < 5; k++) {          // x projection (weights from smem)
            u64 xk = xpp[k];
            fma2(a0, xk, s_wih0[g0 * 5 + k]);
            fma2(a1, xk, s_wih0[g1 * 5 + k]);
            fma2(a2, xk, s_wih0[g2 * 5 + k]);
        }
#pragma unroll
        for (int k = 0; k < 10; k++) {         // recurrent part (weights in regs)
            u64 hk = h1p[k];
            fma2(a0, hk, wh0[0][k]);
            fma2(a1, hk, wh0[1][k]);
            fma2(a2, hk, wh0[2][k]);
        }
        {
            float v0 = act_eval(hadd2(a0), fmc[0], Ac[0], Bcc[0]);
            float v1 = act_eval(hadd2(a1), fmc[1], Ac[1], Bcc[1]);
            float v2 = act_eval(hadd2(a2), fmc[2], Ac[2], Bcc[2]);
            s_g[w][g0] = v0;
            s_g[w][g1] = v1;
            if (lane < 16) s_g[w][g2] = v2;
        }
        __syncwarp();
        if (lane < H) {                        // cell update, lanes 0..19
            float ii = s_g[w][lane];
            float ff = s_g[w][lane + 20];
            float gg = s_g[w][lane + 40];
            float oo = s_g[w][lane + 60];
            c1 = fmaf(ff, c1, ii * gg);
            float th = act_eval(c1, -2.0f, 2.0f, -1.0f);   // tanh(c1)
            s_h1[w][lane] = oo * th;
        }
        __syncwarp();

        // ================= layer 2 gates =================
        a0 = pk2(s_b1[g0], 0.0f);
        a1 = pk2(s_b1[g1], 0.0f);
        a2 = pk2(s_b1[g2], 0.0f);
#pragma unroll
        for (int k = 0; k < 10; k++) {         // input = h1
            u64 hk = h1p[k];
            fma2(a0, hk, wx1[0][k]);
            fma2(a1, hk, wx1[1][k]);
            fma2(a2, hk, wx1[2][k]);
        }
#pragma unroll
        for (int k = 0; k < 10; k++) {         // recurrent = h2
            u64 hk = h2p[k];
            fma2(a0, hk, wh1[0][k]);
            fma2(a1, hk, wh1[1][k]);
            fma2(a2, hk, wh1[2][k]);
        }
        {
            float v0 = act_eval(hadd2(a0), fmc[0], Ac[0], Bcc[0]);
            float v1 = act_eval(hadd2(a1), fmc[1], Ac[1], Bcc[1]);
            float v2 = act_eval(hadd2(a2), fmc[2], Ac[2], Bcc[2]);
            s_g[w][g0] = v0;
            s_g[w][g1] = v1;
            if (lane < 16) s_g[w][g2] = v2;
        }
        __syncwarp();
        if (lane < H) {
            float ii = s_g[w][lane];
            float ff = s_g[w][lane + 20];
            float gg = s_g[w][lane + 40];
            float oo = s_g[w][lane + 60];
            c2 = fmaf(ff, c2, ii * gg);
            float th = act_eval(c2, -2.0f, 2.0f, -1.0f);   // tanh(c2)
            h2v = oo * th;
            s_h2[w][lane] = h2v;
        }
        __syncwarp();
    }

    // ================= FC head: out[b] = h2_last . w_fc + b_fc =================
    float val = (lane < H) ? h2v * wfc : 0.0f;
#pragma unroll
    for (int o = 16; o > 0; o >>= 1)
        val += __shfl_xor_sync(0xffffffffu, val, o);
    if (lane == 0) out[b] = val + b_fc[0];
}

extern "C" void kernel_launch(void* const* d_in, const int* in_sizes, int n_in,
                              void* d_out, int out_size)
{
    const float* x     = (const float*)d_in[0];
    const float* w_ih0 = (const float*)d_in[1];
    const float* w_hh0 = (const float*)d_in[2];
    const float* b_ih0 = (const float*)d_in[3];
    const float* b_hh0 = (const float*)d_in[4];
    const float* w_ih1 = (const float*)d_in[5];
    const float* w_hh1 = (const float*)d_in[6];
    const float* b_ih1 = (const float*)d_in[7];
    const float* b_hh1 = (const float*)d_in[8];
    const float* w_fc  = (const float*)d_in[9];
    const float* b_fc  = (const float*)d_in[10];
    float* out = (float*)d_out;

    const int B = out_size;                    // output is [B, 1]
    const int T = in_sizes[0] / (B * FIN);     // x is [B, T, FIN]

    dim3 grid((B + NW - 1) / NW);
    dim3 block(THREADS);
    lstm2_fused_kernel<<<grid, block>>>(x, w_ih0, w_hh0, b_ih0, b_hh0,
                                        w_ih1, w_hh1, b_ih1, b_hh1,
                                        w_fc, b_fc, out, T, B);
}